// round 1
// baseline (speedup 1.0000x reference)
#include <cuda_runtime.h>
#include <cstdint>

#define B_  16
#define T_  128
#define C_  256
#define HW_ 1024

// ---------------- scratch (static device globals; no cudaMalloc allowed) ----
__device__ float g_Q  [B_ * T_  * HW_];   // Q = F_a@W_aQ+b          (8 MB)
__device__ float g_Ks [B_ * HW_ * HW_];   // K_s = F_s@W_sK+b        (64 MB)
__device__ float g_QK [B_ * T_  * HW_];   // QK -> S -> Kmat (in place)
__device__ float g_Vs [B_ * HW_ * C_];    // V_s scaled by v (Vsv)
__device__ float g_O  [B_ * T_  * C_];    // S_hat @ V_s
__device__ float g_H  [B_ * T_  * 3*C_];  // relu(out@W1+b1)
__device__ float g_u  [B_ * T_];
__device__ float g_v  [B_ * HW_];
__device__ int   g_iter_fallback = 100;

// ---------------- generic SIMT SGEMM: C = A @ B (+bias) (*row_scale) (relu) --
// A row-major [M,K]; B row-major [K,N] (NT=false) or [N,K] (NT=true).
// BM=128, BN=64, BK=16, 256 threads, 8x4 per-thread tile.
template <bool NT>
__global__ __launch_bounds__(256) void sgemm(
    const float* __restrict__ A, const float* __restrict__ Bm,
    const float* __restrict__ bias, const float* __restrict__ rscale,
    float* __restrict__ C,
    int M, int N, int K,
    long long sA, long long sB, long long sC,
    int rsStride, int doRelu)
{
    __shared__ float As[16][128];   // [k][m]
    __shared__ float Bs[16][68];    // [k][n] (padded: 68 keeps 16B align)

    const int bz = blockIdx.z;
    const float* Ab = A  + (long long)bz * sA;
    const float* Bb = Bm + (long long)bz * sB;
    float*       Cb = C  + (long long)bz * sC;

    const int m0 = blockIdx.y * 128;
    const int n0 = blockIdx.x * 64;
    const int tid = threadIdx.x;
    const int tx = tid & 15;     // 0..15 -> n
    const int ty = tid >> 4;     // 0..15 -> m

    float acc[8][4];
#pragma unroll
    for (int i = 0; i < 8; ++i)
#pragma unroll
        for (int j = 0; j < 4; ++j) acc[i][j] = 0.f;

    const int a_k4 = (tid & 3) << 2;   // 0,4,8,12
    const int a_m  = tid >> 2;         // 0..63

    for (int k0 = 0; k0 < K; k0 += 16) {
        // A tile 128x16 -> As[k][m]
#pragma unroll
        for (int r = 0; r < 2; ++r) {
            int m = a_m + (r << 6);
            float4 va = *(const float4*)(Ab + (long long)(m0 + m) * K + (k0 + a_k4));
            As[a_k4 + 0][m] = va.x; As[a_k4 + 1][m] = va.y;
            As[a_k4 + 2][m] = va.z; As[a_k4 + 3][m] = va.w;
        }
        // B tile -> Bs[k][n]
        if (!NT) {
            int b_n4 = (tid & 15) << 2;
            int b_k  = tid >> 4;
            float4 vb = *(const float4*)(Bb + (long long)(k0 + b_k) * N + (n0 + b_n4));
            *(float4*)(&Bs[b_k][b_n4]) = vb;
        } else {
            int b_k4 = (tid & 3) << 2;
            int b_n  = tid >> 2;
            float4 vb = *(const float4*)(Bb + (long long)(n0 + b_n) * K + (k0 + b_k4));
            Bs[b_k4 + 0][b_n] = vb.x; Bs[b_k4 + 1][b_n] = vb.y;
            Bs[b_k4 + 2][b_n] = vb.z; Bs[b_k4 + 3][b_n] = vb.w;
        }
        __syncthreads();

#pragma unroll
        for (int k = 0; k < 16; ++k) {
            float af[8], bf[4];
            *(float4*)&af[0] = *(const float4*)&As[k][ty << 3];
            *(float4*)&af[4] = *(const float4*)&As[k][(ty << 3) + 4];
            *(float4*)&bf[0] = *(const float4*)&Bs[k][tx << 2];
#pragma unroll
            for (int i = 0; i < 8; ++i)
#pragma unroll
                for (int j = 0; j < 4; ++j)
                    acc[i][j] = fmaf(af[i], bf[j], acc[i][j]);
        }
        __syncthreads();
    }

#pragma unroll
    for (int i = 0; i < 8; ++i) {
        int m = m0 + (ty << 3) + i;
        float rs = rscale ? rscale[(long long)bz * rsStride + m] : 1.f;
        float vals[4];
#pragma unroll
        for (int j = 0; j < 4; ++j) {
            float x = acc[i][j];
            if (bias) x += bias[n0 + (tx << 2) + j];
            x *= rs;
            if (doRelu) x = fmaxf(x, 0.f);
            vals[j] = x;
        }
        *(float4*)(Cb + (long long)m * N + n0 + (tx << 2)) = *(float4*)vals;
    }
}

// ---------------- masked softmax -> Kmat = exp(10*S - 10), in place ---------
__global__ __launch_bounds__(256) void softmax_kmat(
    float* __restrict__ ZK, const int* __restrict__ Ms)
{
    __shared__ float red[256];
    const int row = blockIdx.x;        // b*T + t
    const int b   = row >> 7;          // /T_
    float* z = ZK + (long long)row * HW_;
    const int* mrow = Ms + b * HW_;
    const int tid = threadIdx.x;

    float zv[4]; int mv[4];
    float mx = -3.4e38f;
#pragma unroll
    for (int c = 0; c < 4; ++c) {
        int h = tid + (c << 8);
        zv[c] = z[h];
        mv[c] = mrow[h];
        if (mv[c]) mx = fmaxf(mx, zv[c]);
    }
    red[tid] = mx; __syncthreads();
    for (int s = 128; s; s >>= 1) { if (tid < s) red[tid] = fmaxf(red[tid], red[tid + s]); __syncthreads(); }
    mx = red[0]; __syncthreads();

    float ev[4], sum = 0.f;
#pragma unroll
    for (int c = 0; c < 4; ++c) {
        ev[c] = mv[c] ? expf(zv[c] - mx) : 0.f;
        sum += ev[c];
    }
    red[tid] = sum; __syncthreads();
    for (int s = 128; s; s >>= 1) { if (tid < s) red[tid] += red[tid + s]; __syncthreads(); }
    const float inv = 1.f / red[0];

#pragma unroll
    for (int c = 0; c < 4; ++c) {
        int h = tid + (c << 8);
        float S = ev[c] * inv;            // exactly 0 on masked cols
        z[h] = expf(10.f * S - 10.f);     // exp(-(1-S)/0.1)
    }
}

// ---------------- cluster helpers (inline PTX, per sm_103a examples) --------
__device__ __forceinline__ uint32_t smem_u32(const void* p) {
    uint32_t a;
    asm("{ .reg .u64 t; cvta.to.shared.u64 t, %1; cvt.u32.u64 %0, t; }"
        : "=r"(a) : "l"(p));
    return a;
}
__device__ __forceinline__ void cluster_sync_() {
    asm volatile("barrier.cluster.arrive.aligned;" ::: "memory");
    asm volatile("barrier.cluster.wait.aligned;"  ::: "memory");
}
__device__ __forceinline__ float ld_peer_f32(uint32_t addr, uint32_t rank) {
    uint32_t r; float v;
    asm volatile("mapa.shared::cluster.u32 %0, %1, %2;" : "=r"(r) : "r"(addr), "r"(rank));
    asm volatile("ld.shared::cluster.f32 %0, [%1];"     : "=f"(v) : "r"(r));
    return v;
}

// ---------------- Sinkhorn: one 8-CTA cluster per batch, K tile in SMEM -----
// CTA rank owns 128 columns (h); whole T=128 in-tile. One cluster barrier
// per iteration; Kv partials exchanged via double-buffered DSMEM reads.
__global__ void __cluster_dims__(8, 1, 1) __launch_bounds__(256, 1)
sinkhorn(const float* __restrict__ Km, const int* __restrict__ Ms,
         const int* __restrict__ nIterPtr,
         float* __restrict__ gu, float* __restrict__ gv)
{
    extern __shared__ float sm[];
    float* Kt   = sm;                   // 128 * 129
    float* u    = Kt + 128 * 129;       // 128
    float* v    = u  + 128;             // 128
    float* bv   = v  + 128;             // 128
    float* red  = bv + 128;             // 256
    float* pbuf = red + 256;            // 2 * 128 (double-buffered partial Kv)

    const int rank = blockIdx.x;
    const int b    = blockIdx.y;
    const int h0   = rank << 7;
    const int tid  = threadIdx.x;

    // foreground count + target marginal for local columns
    const int* mrow = Ms + b * HW_;
    float msum = 0.f;
    for (int h = tid; h < HW_; h += 256) msum += (float)mrow[h];
    red[tid] = msum; __syncthreads();
    for (int s = 128; s; s >>= 1) { if (tid < s) red[tid] += red[tid + s]; __syncthreads(); }
    const float num_fg = red[0];
    __syncthreads();
    if (tid < 128) {
        bv[tid] = mrow[h0 + tid] ? 1.f / num_fg : 0.f;
        u[tid]  = 1.f / (float)T_;
    }

    // load K tile [T=128][128 local cols], padded row stride 129 (conflict-free both axes)
    const float* Kb = Km + (long long)b * T_ * HW_ + h0;
    for (int idx = tid; idx < 128 * 128; idx += 256) {
        int t = idx >> 7, hl = idx & 127;
        Kt[t * 129 + hl] = Kb[(long long)t * HW_ + hl];
    }
    __syncthreads();

    const int niter = *nIterPtr;
    const int col  = tid & 127;
    const int half = tid >> 7;
    const uint32_t pbuf_addr = smem_u32(pbuf);

    for (int it = 0; it < niter; ++it) {
        const int p = it & 1;

        // phase 1: Ktu_h = sum_t K[t,h]*u[t]  (2 threads per column)
        float s1 = 0.f;
        {
            const float* kp = Kt + (half << 6) * 129 + col;
            const float* up = u + (half << 6);
#pragma unroll 8
            for (int t = 0; t < 64; ++t) s1 = fmaf(kp[t * 129], up[t], s1);
        }
        red[tid] = s1; __syncthreads();
        if (tid < 128) {
            float ktu = red[tid] + red[tid + 128];
            float bb = bv[tid];
            v[tid] = (bb > 0.f) ? bb / ktu : 0.f;
        }
        __syncthreads();

        // phase 2: partial Kv_t over local columns (2 threads per row)
        float s2 = 0.f;
        {
            const float* kp = Kt + col * 129 + (half << 6);
            const float* vp = v + (half << 6);
#pragma unroll 8
            for (int hh = 0; hh < 64; ++hh) s2 = fmaf(kp[hh], vp[hh], s2);
        }
        red[tid] = s2; __syncthreads();
        if (tid < 128) pbuf[(p << 7) + tid] = red[tid] + red[tid + 128];

        cluster_sync_();   // release partials / acquire peers'

        if (tid < 128) {
            float kv = 0.f;
#pragma unroll
            for (int r = 0; r < 8; ++r)
                kv += ld_peer_f32(pbuf_addr + (((p << 7) + tid) << 2), (uint32_t)r);
            u[tid] = (1.f / (float)T_) / kv;
        }
        __syncthreads();
    }

    if (tid < 128) {
        if (rank == 0) gu[b * T_ + tid] = u[tid];
        gv[b * HW_ + h0 + tid] = v[tid];
    }
    cluster_sync_();   // keep SMEM alive until all peers are done reading
}

// ---------------- driver ----------------------------------------------------
extern "C" void kernel_launch(void* const* d_in, const int* in_sizes, int n_in,
                              void* d_out, int out_size)
{
    const float* F_a  = (const float*)d_in[0];
    const float* F_s  = (const float*)d_in[1];
    const int*   M_s  = (const int*)  d_in[2];
    const float* W_aQ = (const float*)d_in[3];
    const float* b_aQ = (const float*)d_in[4];
    const float* W_sK = (const float*)d_in[5];
    const float* b_sK = (const float*)d_in[6];
    const float* W_sV = (const float*)d_in[7];
    const float* b_sV = (const float*)d_in[8];
    const float* W1   = (const float*)d_in[9];
    const float* b1   = (const float*)d_in[10];
    const float* W2   = (const float*)d_in[11];
    const float* b2   = (const float*)d_in[12];
    float* y = (float*)d_out;

    float *Q, *Ks, *QK, *Vs, *O, *H, *u, *v; int* itf;
    cudaGetSymbolAddress((void**)&Q,  g_Q);
    cudaGetSymbolAddress((void**)&Ks, g_Ks);
    cudaGetSymbolAddress((void**)&QK, g_QK);
    cudaGetSymbolAddress((void**)&Vs, g_Vs);
    cudaGetSymbolAddress((void**)&O,  g_O);
    cudaGetSymbolAddress((void**)&H,  g_H);
    cudaGetSymbolAddress((void**)&u,  g_u);
    cudaGetSymbolAddress((void**)&v,  g_v);
    cudaGetSymbolAddress((void**)&itf, g_iter_fallback);

    const int* iterp = (n_in > 13 && d_in[13]) ? (const int*)d_in[13]
                                               : (const int*)itf;

    const int SK_SMEM = (128 * 129 + 128 * 3 + 256 + 256) * 4;  // 69632 B
    cudaFuncSetAttribute(sinkhorn, cudaFuncAttributeMaxDynamicSharedMemorySize, SK_SMEM);

    // 1) Q = F_a @ W_aQ + b_aQ               [2048,256]@[256,1024]
    sgemm<false><<<dim3(HW_ / 64, (B_ * T_) / 128, 1), 256>>>(
        F_a, W_aQ, b_aQ, nullptr, Q, B_ * T_, HW_, C_, 0, 0, 0, 0, 0);
    // 2) K_s = F_s @ W_sK + b_sK             [16384,256]@[256,1024]
    sgemm<false><<<dim3(HW_ / 64, (B_ * HW_) / 128, 1), 256>>>(
        F_s, W_sK, b_sK, nullptr, Ks, B_ * HW_, HW_, C_, 0, 0, 0, 0, 0);
    // 3) QK[b] = Q[b] @ K_s[b]^T  (batched NT, contract over h=1024)
    sgemm<true><<<dim3(HW_ / 64, 1, B_), 256>>>(
        Q, Ks, nullptr, nullptr, QK, T_, HW_, HW_,
        (long long)T_ * HW_, (long long)HW_ * HW_, (long long)T_ * HW_, 0, 0);
    // 4) masked softmax -> Kmat (in place over QK)
    softmax_kmat<<<B_ * T_, 256>>>(QK, M_s);
    // 5) Sinkhorn OT (persistent, cluster-per-batch) -> u, v
    sinkhorn<<<dim3(8, B_), 256, SK_SMEM>>>(QK, M_s, iterp, u, v);
    // 6) Vsv = (F_s @ W_sV + b_sV) * v[row]  (row index = b*HW+h, flat)
    sgemm<false><<<dim3(C_ / 64, (B_ * HW_) / 128, 1), 256>>>(
        F_s, W_sV, b_sV, v, Vs, B_ * HW_, C_, C_, 0, 0, 0, 0, 0);
    // 7) out[b] = (Kmat[b] @ Vsv[b]) * u[b,t]  (batched NN)
    sgemm<false><<<dim3(C_ / 64, 1, B_), 256>>>(
        QK, Vs, nullptr, u, O, T_, C_, HW_,
        (long long)T_ * HW_, (long long)HW_ * C_, (long long)T_ * C_, T_, 0);
    // 8) H = relu(out @ W1 + b1)             [2048,256]@[256,768]
    sgemm<false><<<dim3((3 * C_) / 64, (B_ * T_) / 128, 1), 256>>>(
        O, W1, b1, nullptr, H, B_ * T_, 3 * C_, C_, 0, 0, 0, 0, 1);
    // 9) y = H @ W2 + b2 -> d_out            [2048,768]@[768,256]
    sgemm<false><<<dim3(C_ / 64, (B_ * T_) / 128, 1), 256>>>(
        H, W2, b2, nullptr, y, B_ * T_, C_, 3 * C_, 0, 0, 0, 0, 0);
}

// round 4
// speedup vs baseline: 1.3334x; 1.3334x over previous
#include <cuda_runtime.h>
#include <cstdint>

#define B_  16
#define T_  128
#define C_  256
#define HW_ 1024

// ---------------- scratch (static device globals; no cudaMalloc allowed) ----
__device__ float g_P   [B_ * T_  * HW_];   // P = F_a@W_aQ + b_aQ       (8 MB)
__device__ float g_WkT [HW_ * C_];         // W_sK^T [HW, C]            (1 MB)
__device__ float g_FsT [B_ * C_ * HW_];    // F_s^T per batch [C, HW]  (16 MB)
__device__ float g_Qw  [B_ * T_  * C_];    // Qw = P @ W_sK^T           (2 MB)
__device__ float g_QK  [B_ * T_  * HW_];   // QK -> S -> Kmat           (8 MB)
__device__ float g_Vs  [B_ * HW_ * C_];    // (F_s@W_sV + b_sV) * v    (16 MB)
__device__ float g_O   [B_ * T_  * C_];    // (Kmat@Vsv) * u
__device__ float g_H   [B_ * T_  * 3*C_];  // relu(O@W1+b1)
__device__ float g_u   [B_ * T_];
__device__ float g_v   [B_ * HW_];
__device__ int   g_iter_fallback = 100;

// ---------------- SIMT SGEMM (ROUND-1 VALIDATED, verbatim; NN used only) ----
// C = rscale ⊙ (A @ B + bias). A row-major [M,K]; B row-major [K,N] (NN).
// BM=128, BN=64, BK=16, 256 threads, 8x4 per-thread tile.
template <bool NT>
__global__ __launch_bounds__(256) void sgemm(
    const float* __restrict__ A, const float* __restrict__ Bm,
    const float* __restrict__ bias, const float* __restrict__ rscale,
    float* __restrict__ C,
    int M, int N, int K,
    long long sA, long long sB, long long sC,
    int rsStride, int doRelu)
{
    __shared__ float As[16][128];   // [k][m]
    __shared__ float Bs[16][68];    // [k][n]

    const int bz = blockIdx.z;
    const float* Ab = A  + (long long)bz * sA;
    const float* Bb = Bm + (long long)bz * sB;
    float*       Cb = C  + (long long)bz * sC;

    const int m0 = blockIdx.y * 128;
    const int n0 = blockIdx.x * 64;
    const int tid = threadIdx.x;
    const int tx = tid & 15;
    const int ty = tid >> 4;

    float acc[8][4];
#pragma unroll
    for (int i = 0; i < 8; ++i)
#pragma unroll
        for (int j = 0; j < 4; ++j) acc[i][j] = 0.f;

    const int a_k4 = (tid & 3) << 2;
    const int a_m  = tid >> 2;

    for (int k0 = 0; k0 < K; k0 += 16) {
#pragma unroll
        for (int r = 0; r < 2; ++r) {
            int m = a_m + (r << 6);
            float4 va = *(const float4*)(Ab + (long long)(m0 + m) * K + (k0 + a_k4));
            As[a_k4 + 0][m] = va.x; As[a_k4 + 1][m] = va.y;
            As[a_k4 + 2][m] = va.z; As[a_k4 + 3][m] = va.w;
        }
        if (!NT) {
            int b_n4 = (tid & 15) << 2;
            int b_k  = tid >> 4;
            float4 vb = *(const float4*)(Bb + (long long)(k0 + b_k) * N + (n0 + b_n4));
            *(float4*)(&Bs[b_k][b_n4]) = vb;
        } else {
            int b_k4 = (tid & 3) << 2;
            int b_n  = tid >> 2;
            float4 vb = *(const float4*)(Bb + (long long)(n0 + b_n) * K + (k0 + b_k4));
            Bs[b_k4 + 0][b_n] = vb.x; Bs[b_k4 + 1][b_n] = vb.y;
            Bs[b_k4 + 2][b_n] = vb.z; Bs[b_k4 + 3][b_n] = vb.w;
        }
        __syncthreads();

#pragma unroll
        for (int k = 0; k < 16; ++k) {
            float af[8], bf[4];
            *(float4*)&af[0] = *(const float4*)&As[k][ty << 3];
            *(float4*)&af[4] = *(const float4*)&As[k][(ty << 3) + 4];
            *(float4*)&bf[0] = *(const float4*)&Bs[k][tx << 2];
#pragma unroll
            for (int i = 0; i < 8; ++i)
#pragma unroll
                for (int j = 0; j < 4; ++j)
                    acc[i][j] = fmaf(af[i], bf[j], acc[i][j]);
        }
        __syncthreads();
    }

#pragma unroll
    for (int i = 0; i < 8; ++i) {
        int m = m0 + (ty << 3) + i;
        float rs = rscale ? rscale[(long long)bz * rsStride + m] : 1.f;
        float vals[4];
#pragma unroll
        for (int j = 0; j < 4; ++j) {
            float x = acc[i][j];
            if (bias) x += bias[n0 + (tx << 2) + j];
            x *= rs;
            if (doRelu) x = fmaxf(x, 0.f);
            vals[j] = x;
        }
        *(float4*)(Cb + (long long)m * N + n0 + (tx << 2)) = *(float4*)vals;
    }
}

// ---------------- tiled transpose: out[Cc,R] = in[R,Cc]^T (per batch z) -----
__global__ __launch_bounds__(256) void transpose_k(
    const float* __restrict__ in, float* __restrict__ out,
    int R, int Cc, long long sIn, long long sOut)
{
    __shared__ float t[32][33];
    const float* ib = in  + (long long)blockIdx.z * sIn;
    float*       ob = out + (long long)blockIdx.z * sOut;
    const int r0 = blockIdx.y << 5;
    const int c0 = blockIdx.x << 5;
    const int lx = threadIdx.x & 31;
    const int ly = threadIdx.x >> 5;   // 0..7
#pragma unroll
    for (int i = ly; i < 32; i += 8)
        t[i][lx] = ib[(long long)(r0 + i) * Cc + (c0 + lx)];
    __syncthreads();
#pragma unroll
    for (int i = ly; i < 32; i += 8)
        ob[(long long)(c0 + i) * R + (r0 + lx)] = t[lx][i];
}

// ---------------- masked softmax -> Kmat = exp(10*S - 10), in place ---------
__global__ __launch_bounds__(256) void softmax_kmat(
    float* __restrict__ ZK, const int* __restrict__ Ms)
{
    __shared__ float red[256];
    const int row = blockIdx.x;        // b*T + t
    const int b   = row >> 7;
    float* z = ZK + (long long)row * HW_;
    const int* mrow = Ms + b * HW_;
    const int tid = threadIdx.x;

    float zv[4]; int mv[4];
    float mx = -3.4e38f;
#pragma unroll
    for (int c = 0; c < 4; ++c) {
        int h = tid + (c << 8);
        zv[c] = z[h];
        mv[c] = mrow[h];
        if (mv[c]) mx = fmaxf(mx, zv[c]);
    }
    red[tid] = mx; __syncthreads();
    for (int s = 128; s; s >>= 1) { if (tid < s) red[tid] = fmaxf(red[tid], red[tid + s]); __syncthreads(); }
    mx = red[0]; __syncthreads();

    float ev[4], sum = 0.f;
#pragma unroll
    for (int c = 0; c < 4; ++c) {
        ev[c] = mv[c] ? expf(zv[c] - mx) : 0.f;
        sum += ev[c];
    }
    red[tid] = sum; __syncthreads();
    for (int s = 128; s; s >>= 1) { if (tid < s) red[tid] += red[tid + s]; __syncthreads(); }
    const float inv = 1.f / red[0];

#pragma unroll
    for (int c = 0; c < 4; ++c) {
        int h = tid + (c << 8);
        float S = ev[c] * inv;
        z[h] = expf(10.f * S - 10.f);     // exp(-(1-S)/0.1)
    }
}

// ---------------- cluster helpers --------------------------------------------
__device__ __forceinline__ uint32_t smem_u32(const void* p) {
    uint32_t a;
    asm("{ .reg .u64 t; cvta.to.shared.u64 t, %1; cvt.u32.u64 %0, t; }"
        : "=r"(a) : "l"(p));
    return a;
}
__device__ __forceinline__ void cluster_sync_() {
    asm volatile("barrier.cluster.arrive.aligned;" ::: "memory");
    asm volatile("barrier.cluster.wait.aligned;"  ::: "memory");
}
__device__ __forceinline__ float ld_peer_f32(uint32_t addr, uint32_t rank) {
    uint32_t r; float v;
    asm volatile("mapa.shared::cluster.u32 %0, %1, %2;" : "=r"(r) : "r"(addr), "r"(rank));
    asm volatile("ld.shared::cluster.f32 %0, [%1];"     : "=f"(v) : "r"(r));
    return v;
}

// ---------------- Sinkhorn (ROUND-1 VALIDATED, verbatim) --------------------
__global__ void __cluster_dims__(8, 1, 1) __launch_bounds__(256, 1)
sinkhorn(const float* __restrict__ Km, const int* __restrict__ Ms,
         const int* __restrict__ nIterPtr,
         float* __restrict__ gu, float* __restrict__ gv)
{
    extern __shared__ float sm[];
    float* Kt   = sm;                   // 128 * 129
    float* u    = Kt + 128 * 129;       // 128
    float* v    = u  + 128;             // 128
    float* bv   = v  + 128;             // 128
    float* red  = bv + 128;             // 256
    float* pbuf = red + 256;            // 2 * 128

    const int rank = blockIdx.x;
    const int b    = blockIdx.y;
    const int h0   = rank << 7;
    const int tid  = threadIdx.x;

    const int* mrow = Ms + b * HW_;
    float msum = 0.f;
    for (int h = tid; h < HW_; h += 256) msum += (float)mrow[h];
    red[tid] = msum; __syncthreads();
    for (int s = 128; s; s >>= 1) { if (tid < s) red[tid] += red[tid + s]; __syncthreads(); }
    const float num_fg = red[0];
    __syncthreads();
    if (tid < 128) {
        bv[tid] = mrow[h0 + tid] ? 1.f / num_fg : 0.f;
        u[tid]  = 1.f / (float)T_;
    }

    const float* Kb = Km + (long long)b * T_ * HW_ + h0;
    for (int idx = tid; idx < 128 * 128; idx += 256) {
        int t = idx >> 7, hl = idx & 127;
        Kt[t * 129 + hl] = Kb[(long long)t * HW_ + hl];
    }
    __syncthreads();

    const int niter = *nIterPtr;
    const int col  = tid & 127;
    const int half = tid >> 7;
    const uint32_t pbuf_addr = smem_u32(pbuf);

    for (int it = 0; it < niter; ++it) {
        const int p = it & 1;

        float s1 = 0.f;
        {
            const float* kp = Kt + (half << 6) * 129 + col;
            const float* up = u + (half << 6);
#pragma unroll 8
            for (int t = 0; t < 64; ++t) s1 = fmaf(kp[t * 129], up[t], s1);
        }
        red[tid] = s1; __syncthreads();
        if (tid < 128) {
            float ktu = red[tid] + red[tid + 128];
            float bb = bv[tid];
            v[tid] = (bb > 0.f) ? bb / ktu : 0.f;
        }
        __syncthreads();

        float s2 = 0.f;
        {
            const float* kp = Kt + col * 129 + (half << 6);
            const float* vp = v + (half << 6);
#pragma unroll 8
            for (int hh = 0; hh < 64; ++hh) s2 = fmaf(kp[hh], vp[hh], s2);
        }
        red[tid] = s2; __syncthreads();
        if (tid < 128) pbuf[(p << 7) + tid] = red[tid] + red[tid + 128];

        cluster_sync_();

        if (tid < 128) {
            float kv = 0.f;
#pragma unroll
            for (int r = 0; r < 8; ++r)
                kv += ld_peer_f32(pbuf_addr + (((p << 7) + tid) << 2), (uint32_t)r);
            u[tid] = (1.f / (float)T_) / kv;
        }
        __syncthreads();
    }

    if (tid < 128) {
        if (rank == 0) gu[b * T_ + tid] = u[tid];
        gv[b * HW_ + h0 + tid] = v[tid];
    }
    cluster_sync_();
}

// ---------------- driver ------------------------------------------------------
extern "C" void kernel_launch(void* const* d_in, const int* in_sizes, int n_in,
                              void* d_out, int out_size)
{
    const float* F_a  = (const float*)d_in[0];
    const float* F_s  = (const float*)d_in[1];
    const int*   M_s  = (const int*)  d_in[2];
    const float* W_aQ = (const float*)d_in[3];
    const float* b_aQ = (const float*)d_in[4];
    const float* W_sK = (const float*)d_in[5];
    // d_in[6] = b_sK : per-(b,t)-row logit constant, cancels in softmax over k
    const float* W_sV = (const float*)d_in[7];
    const float* b_sV = (const float*)d_in[8];
    const float* W1   = (const float*)d_in[9];
    const float* b1   = (const float*)d_in[10];
    const float* W2   = (const float*)d_in[11];
    const float* b2   = (const float*)d_in[12];
    float* y = (float*)d_out;

    float *P, *WkT, *FsT, *Qw, *QK, *Vs, *O, *H, *u, *v; int* itf;
    cudaGetSymbolAddress((void**)&P,   g_P);
    cudaGetSymbolAddress((void**)&WkT, g_WkT);
    cudaGetSymbolAddress((void**)&FsT, g_FsT);
    cudaGetSymbolAddress((void**)&Qw,  g_Qw);
    cudaGetSymbolAddress((void**)&QK,  g_QK);
    cudaGetSymbolAddress((void**)&Vs,  g_Vs);
    cudaGetSymbolAddress((void**)&O,   g_O);
    cudaGetSymbolAddress((void**)&H,   g_H);
    cudaGetSymbolAddress((void**)&u,   g_u);
    cudaGetSymbolAddress((void**)&v,   g_v);
    cudaGetSymbolAddress((void**)&itf, g_iter_fallback);

    const int* iterp = (n_in > 13 && d_in[13]) ? (const int*)d_in[13]
                                               : (const int*)itf;

    const int SK_SMEM = (128 * 129 + 128 * 3 + 256 + 256) * 4;  // 69632 B
    cudaFuncSetAttribute(sinkhorn, cudaFuncAttributeMaxDynamicSharedMemorySize, SK_SMEM);

    // 0a) WkT = W_sK^T                 [256,1024] -> [1024,256]
    transpose_k<<<dim3(HW_ / 32, C_ / 32, 1), 256>>>(W_sK, WkT, C_, HW_, 0, 0);
    // 0b) FsT[b] = F_s[b]^T            [1024,256] -> [256,1024], batched
    transpose_k<<<dim3(C_ / 32, HW_ / 32, B_), 256>>>(
        F_s, FsT, HW_, C_, (long long)HW_ * C_, (long long)C_ * HW_);

    // 1) P = F_a @ W_aQ + b_aQ         [2048,1024] k=256 (NN)
    sgemm<false><<<dim3(16, 16, 1), 256>>>(
        F_a, W_aQ, b_aQ, nullptr, P, B_ * T_, HW_, C_, 0, 0, 0, 0, 0);

    // 2) Qw = P @ WkT                  [2048,256] k=1024 (NN)
    sgemm<false><<<dim3(4, 16, 1), 256>>>(
        P, WkT, nullptr, nullptr, Qw, B_ * T_, C_, HW_, 0, 0, 0, 0, 0);

    // 3) QK[b] = Qw[b] @ FsT[b]        batched [128,1024] k=256 (NN)
    sgemm<false><<<dim3(16, 1, B_), 256>>>(
        Qw, FsT, nullptr, nullptr, QK, T_, HW_, C_,
        (long long)T_ * C_, (long long)C_ * HW_, (long long)T_ * HW_, 0, 0);

    // 4) masked softmax -> Kmat (in place)
    softmax_kmat<<<B_ * T_, 256>>>(QK, M_s);

    // 5) Sinkhorn OT -> u, v
    sinkhorn<<<dim3(8, B_), 256, SK_SMEM>>>(QK, M_s, iterp, u, v);

    // 6) Vsv = (F_s @ W_sV + b_sV) * v[row]   (R1-validated, rscale=v flat)
    sgemm<false><<<dim3(C_ / 64, (B_ * HW_) / 128, 1), 256>>>(
        F_s, W_sV, b_sV, v, Vs, B_ * HW_, C_, C_, 0, 0, 0, 0, 0);

    // 7) O[b] = (Kmat[b] @ Vsv[b]) * u[b,t]   (R1-validated, batched NN)
    sgemm<false><<<dim3(C_ / 64, 1, B_), 256>>>(
        QK, Vs, nullptr, u, O, T_, C_, HW_,
        (long long)T_ * HW_, (long long)HW_ * C_, (long long)T_ * C_, T_, 0);

    // 8) H = relu(O @ W1 + b1)         [2048,768] k=256 (NN)
    sgemm<false><<<dim3(12, 16, 1), 256>>>(
        O, W1, b1, nullptr, H, B_ * T_, 3 * C_, C_, 0, 0, 0, 0, 1);

    // 9) y = H @ W2 + b2 -> d_out      [2048,256] k=768 (NN)
    sgemm<false><<<dim3(4, 16, 1), 256>>>(
        H, W2, b2, nullptr, y, B_ * T_, C_, 3 * C_, 0, 0, 0, 0, 0);
}

// round 5
// speedup vs baseline: 1.7140x; 1.2854x over previous
#include <cuda_runtime.h>
#include <cstdint>

#define B_  16
#define T_  128
#define C_  256
#define HW_ 1024

// ---------------- scratch (static device globals; no cudaMalloc allowed) ----
__device__ float g_WkT  [HW_ * C_];         // W_sK^T [HW, C]
__device__ float g_FsT  [B_ * C_ * HW_];    // F_s^T per batch [C, HW]
__device__ float g_Wc   [C_ * C_];          // Wcomb = W_aQ @ WkT
__device__ float g_bc   [C_];               // bcomb = b_aQ @ WkT
__device__ float g_bsV  [C_];               // b_sV / T
__device__ float g_Qw   [B_ * T_  * C_];    // Qw = F_a @ Wcomb + bcomb
__device__ float g_QK   [B_ * T_  * HW_];   // QK -> S -> Kmat -> S_hat
__device__ float g_G    [B_ * T_  * C_];    // S_hat @ F_s
__device__ float g_O    [B_ * T_  * C_];    // G @ W_sV + b_sV/T
__device__ float g_H    [B_ * T_  * 3*C_];  // relu(O@W1+b1)
__device__ float g_u    [B_ * T_];
__device__ float g_v    [B_ * HW_];
__device__ int   g_iter_fallback = 100;

// ---------------- SIMT SGEMM, NN only (validated core; BM templated) --------
// C = rscale ⊙ (A @ B + bias), optional relu.
// A row-major [M,K]; B row-major [K,N]. BM in {128,64}, BN=64, BK=16,
// 256 threads, (BM/16)x4 per-thread tile. At BM=128 this is the round-1/4
// validated kernel verbatim.
template <int BM>
__global__ __launch_bounds__(256) void sgemm(
    const float* __restrict__ A, const float* __restrict__ Bm,
    const float* __restrict__ bias, const float* __restrict__ rscale,
    float* __restrict__ C,
    int M, int N, int K,
    long long sA, long long sB, long long sC,
    int rsStride, int doRelu)
{
    constexpr int TM = BM / 16;
    __shared__ float As[16][BM];    // [k][m]
    __shared__ float Bs[16][68];    // [k][n]

    const int bz = blockIdx.z;
    const float* Ab = A  + (long long)bz * sA;
    const float* Bb = Bm + (long long)bz * sB;
    float*       Cb = C  + (long long)bz * sC;

    const int m0 = blockIdx.y * BM;
    const int n0 = blockIdx.x * 64;
    const int tid = threadIdx.x;
    const int tx = tid & 15;
    const int ty = tid >> 4;

    float acc[TM][4];
#pragma unroll
    for (int i = 0; i < TM; ++i)
#pragma unroll
        for (int j = 0; j < 4; ++j) acc[i][j] = 0.f;

    const int a_k4 = (tid & 3) << 2;
    const int a_m  = tid >> 2;

    for (int k0 = 0; k0 < K; k0 += 16) {
        // A tile BMx16 -> As[k][m]
#pragma unroll
        for (int r = 0; r < BM / 64; ++r) {
            int m = a_m + (r << 6);
            float4 va = *(const float4*)(Ab + (long long)(m0 + m) * K + (k0 + a_k4));
            As[a_k4 + 0][m] = va.x; As[a_k4 + 1][m] = va.y;
            As[a_k4 + 2][m] = va.z; As[a_k4 + 3][m] = va.w;
        }
        // B tile 16x64 -> Bs[k][n]
        {
            int b_n4 = (tid & 15) << 2;
            int b_k  = tid >> 4;
            float4 vb = *(const float4*)(Bb + (long long)(k0 + b_k) * N + (n0 + b_n4));
            *(float4*)(&Bs[b_k][b_n4]) = vb;
        }
        __syncthreads();

#pragma unroll
        for (int k = 0; k < 16; ++k) {
            float af[TM], bf[4];
#pragma unroll
            for (int i = 0; i < TM; i += 4)
                *(float4*)&af[i] = *(const float4*)&As[k][ty * TM + i];
            *(float4*)&bf[0] = *(const float4*)&Bs[k][tx << 2];
#pragma unroll
            for (int i = 0; i < TM; ++i)
#pragma unroll
                for (int j = 0; j < 4; ++j)
                    acc[i][j] = fmaf(af[i], bf[j], acc[i][j]);
        }
        __syncthreads();
    }

#pragma unroll
    for (int i = 0; i < TM; ++i) {
        int m = m0 + ty * TM + i;
        float rs = rscale ? rscale[(long long)bz * rsStride + m] : 1.f;
        float vals[4];
#pragma unroll
        for (int j = 0; j < 4; ++j) {
            float x = acc[i][j];
            if (bias) x += bias[n0 + (tx << 2) + j];
            x *= rs;
            if (doRelu) x = fmaxf(x, 0.f);
            vals[j] = x;
        }
        *(float4*)(Cb + (long long)m * N + n0 + (tx << 2)) = *(float4*)vals;
    }
}

// ---------------- tiled transpose: out[Cc,R] = in[R,Cc]^T (per batch z) -----
__global__ __launch_bounds__(256) void transpose_k(
    const float* __restrict__ in, float* __restrict__ out,
    int R, int Cc, long long sIn, long long sOut)
{
    __shared__ float t[32][33];
    const float* ib = in  + (long long)blockIdx.z * sIn;
    float*       ob = out + (long long)blockIdx.z * sOut;
    const int r0 = blockIdx.y << 5;
    const int c0 = blockIdx.x << 5;
    const int lx = threadIdx.x & 31;
    const int ly = threadIdx.x >> 5;
#pragma unroll
    for (int i = ly; i < 32; i += 8)
        t[i][lx] = ib[(long long)(r0 + i) * Cc + (c0 + lx)];
    __syncthreads();
#pragma unroll
    for (int i = ly; i < 32; i += 8)
        ob[(long long)(c0 + i) * R + (r0 + lx)] = t[lx][i];
}

// ---------------- small vector kernels ---------------------------------------
// bcomb[c] = sum_h b_aQ[h] * W_sK[c,h]
__global__ __launch_bounds__(256) void bcomb_kernel(
    const float* __restrict__ W_sK, const float* __restrict__ b_aQ,
    float* __restrict__ bc)
{
    __shared__ float red[256];
    const int c = blockIdx.x;
    const int tid = threadIdx.x;
    const float* row = W_sK + (long long)c * HW_;
    float s = 0.f;
#pragma unroll
    for (int r = 0; r < 4; ++r) {
        int h = tid + (r << 8);
        s = fmaf(row[h], b_aQ[h], s);
    }
    red[tid] = s; __syncthreads();
    for (int st = 128; st; st >>= 1) { if (tid < st) red[tid] += red[tid + st]; __syncthreads(); }
    if (tid == 0) bc[c] = red[0];
}

__global__ __launch_bounds__(256) void bscale_kernel(
    const float* __restrict__ bin, float* __restrict__ bout, float s)
{
    int i = threadIdx.x;
    if (i < C_) bout[i] = bin[i] * s;
}

// ---------------- masked softmax -> Kmat = exp(10*S - 10), in place ---------
__global__ __launch_bounds__(256) void softmax_kmat(
    float* __restrict__ ZK, const int* __restrict__ Ms)
{
    __shared__ float red[256];
    const int row = blockIdx.x;        // b*T + t
    const int b   = row >> 7;
    float* z = ZK + (long long)row * HW_;
    const int* mrow = Ms + b * HW_;
    const int tid = threadIdx.x;

    float zv[4]; int mv[4];
    float mx = -3.4e38f;
#pragma unroll
    for (int c = 0; c < 4; ++c) {
        int h = tid + (c << 8);
        zv[c] = z[h];
        mv[c] = mrow[h];
        if (mv[c]) mx = fmaxf(mx, zv[c]);
    }
    red[tid] = mx; __syncthreads();
    for (int s = 128; s; s >>= 1) { if (tid < s) red[tid] = fmaxf(red[tid], red[tid + s]); __syncthreads(); }
    mx = red[0]; __syncthreads();

    float ev[4], sum = 0.f;
#pragma unroll
    for (int c = 0; c < 4; ++c) {
        ev[c] = mv[c] ? expf(zv[c] - mx) : 0.f;
        sum += ev[c];
    }
    red[tid] = sum; __syncthreads();
    for (int s = 128; s; s >>= 1) { if (tid < s) red[tid] += red[tid + s]; __syncthreads(); }
    const float inv = 1.f / red[0];

#pragma unroll
    for (int c = 0; c < 4; ++c) {
        int h = tid + (c << 8);
        float S = ev[c] * inv;
        z[h] = expf(10.f * S - 10.f);     // exp(-(1-S)/0.1)
    }
}

// ---------------- S_hat = u ⊙ Kmat ⊙ v, in place ----------------------------
__global__ __launch_bounds__(256) void scale_uv(
    float* __restrict__ Km, const float* __restrict__ u,
    const float* __restrict__ v)
{
    const int row = blockIdx.x;        // b*T + t
    const int b   = row >> 7;
    float* z = Km + (long long)row * HW_;
    const float* vb = v + b * HW_;
    const float ut = u[row];
    const int tid = threadIdx.x;
#pragma unroll
    for (int c = 0; c < 4; ++c) {
        int h = tid + (c << 8);
        z[h] = ut * z[h] * vb[h];
    }
}

// ---------------- cluster helpers --------------------------------------------
__device__ __forceinline__ uint32_t smem_u32(const void* p) {
    uint32_t a;
    asm("{ .reg .u64 t; cvta.to.shared.u64 t, %1; cvt.u32.u64 %0, t; }"
        : "=r"(a) : "l"(p));
    return a;
}
__device__ __forceinline__ void cluster_sync_() {
    asm volatile("barrier.cluster.arrive.aligned;" ::: "memory");
    asm volatile("barrier.cluster.wait.aligned;"  ::: "memory");
}
__device__ __forceinline__ float ld_peer_f32(uint32_t addr, uint32_t rank) {
    uint32_t r; float v;
    asm volatile("mapa.shared::cluster.u32 %0, %1, %2;" : "=r"(r) : "r"(addr), "r"(rank));
    asm volatile("ld.shared::cluster.f32 %0, [%1];"     : "=f"(v) : "r"(r));
    return v;
}

// ---------------- Sinkhorn (validated, verbatim) -----------------------------
__global__ void __cluster_dims__(8, 1, 1) __launch_bounds__(256, 1)
sinkhorn(const float* __restrict__ Km, const int* __restrict__ Ms,
         const int* __restrict__ nIterPtr,
         float* __restrict__ gu, float* __restrict__ gv)
{
    extern __shared__ float sm[];
    float* Kt   = sm;                   // 128 * 129
    float* u    = Kt + 128 * 129;       // 128
    float* v    = u  + 128;             // 128
    float* bv   = v  + 128;             // 128
    float* red  = bv + 128;             // 256
    float* pbuf = red + 256;            // 2 * 128

    const int rank = blockIdx.x;
    const int b    = blockIdx.y;
    const int h0   = rank << 7;
    const int tid  = threadIdx.x;

    const int* mrow = Ms + b * HW_;
    float msum = 0.f;
    for (int h = tid; h < HW_; h += 256) msum += (float)mrow[h];
    red[tid] = msum; __syncthreads();
    for (int s = 128; s; s >>= 1) { if (tid < s) red[tid] += red[tid + s]; __syncthreads(); }
    const float num_fg = red[0];
    __syncthreads();
    if (tid < 128) {
        bv[tid] = mrow[h0 + tid] ? 1.f / num_fg : 0.f;
        u[tid]  = 1.f / (float)T_;
    }

    const float* Kb = Km + (long long)b * T_ * HW_ + h0;
    for (int idx = tid; idx < 128 * 128; idx += 256) {
        int t = idx >> 7, hl = idx & 127;
        Kt[t * 129 + hl] = Kb[(long long)t * HW_ + hl];
    }
    __syncthreads();

    const int niter = *nIterPtr;
    const int col  = tid & 127;
    const int half = tid >> 7;
    const uint32_t pbuf_addr = smem_u32(pbuf);

    for (int it = 0; it < niter; ++it) {
        const int p = it & 1;

        float s1 = 0.f;
        {
            const float* kp = Kt + (half << 6) * 129 + col;
            const float* up = u + (half << 6);
#pragma unroll 8
            for (int t = 0; t < 64; ++t) s1 = fmaf(kp[t * 129], up[t], s1);
        }
        red[tid] = s1; __syncthreads();
        if (tid < 128) {
            float ktu = red[tid] + red[tid + 128];
            float bb = bv[tid];
            v[tid] = (bb > 0.f) ? bb / ktu : 0.f;
        }
        __syncthreads();

        float s2 = 0.f;
        {
            const float* kp = Kt + col * 129 + (half << 6);
            const float* vp = v + (half << 6);
#pragma unroll 8
            for (int hh = 0; hh < 64; ++hh) s2 = fmaf(kp[hh], vp[hh], s2);
        }
        red[tid] = s2; __syncthreads();
        if (tid < 128) pbuf[(p << 7) + tid] = red[tid] + red[tid + 128];

        cluster_sync_();

        if (tid < 128) {
            float kv = 0.f;
#pragma unroll
            for (int r = 0; r < 8; ++r)
                kv += ld_peer_f32(pbuf_addr + (((p << 7) + tid) << 2), (uint32_t)r);
            u[tid] = (1.f / (float)T_) / kv;
        }
        __syncthreads();
    }

    if (tid < 128) {
        if (rank == 0) gu[b * T_ + tid] = u[tid];
        gv[b * HW_ + h0 + tid] = v[tid];
    }
    cluster_sync_();
}

// ---------------- driver ------------------------------------------------------
extern "C" void kernel_launch(void* const* d_in, const int* in_sizes, int n_in,
                              void* d_out, int out_size)
{
    const float* F_a  = (const float*)d_in[0];
    const float* F_s  = (const float*)d_in[1];
    const int*   M_s  = (const int*)  d_in[2];
    const float* W_aQ = (const float*)d_in[3];
    const float* b_aQ = (const float*)d_in[4];
    const float* W_sK = (const float*)d_in[5];
    // d_in[6] = b_sK : per-(b,t)-row logit constant, cancels in softmax over k
    const float* W_sV = (const float*)d_in[7];
    const float* b_sV = (const float*)d_in[8];
    const float* W1   = (const float*)d_in[9];
    const float* b1   = (const float*)d_in[10];
    const float* W2   = (const float*)d_in[11];
    const float* b2   = (const float*)d_in[12];
    float* y = (float*)d_out;

    float *WkT, *FsT, *Wc, *bc, *bsV, *Qw, *QK, *G, *O, *H, *u, *v; int* itf;
    cudaGetSymbolAddress((void**)&WkT, g_WkT);
    cudaGetSymbolAddress((void**)&FsT, g_FsT);
    cudaGetSymbolAddress((void**)&Wc,  g_Wc);
    cudaGetSymbolAddress((void**)&bc,  g_bc);
    cudaGetSymbolAddress((void**)&bsV, g_bsV);
    cudaGetSymbolAddress((void**)&Qw,  g_Qw);
    cudaGetSymbolAddress((void**)&QK,  g_QK);
    cudaGetSymbolAddress((void**)&G,   g_G);
    cudaGetSymbolAddress((void**)&O,   g_O);
    cudaGetSymbolAddress((void**)&H,   g_H);
    cudaGetSymbolAddress((void**)&u,   g_u);
    cudaGetSymbolAddress((void**)&v,   g_v);
    cudaGetSymbolAddress((void**)&itf, g_iter_fallback);

    const int* iterp = (n_in > 13 && d_in[13]) ? (const int*)d_in[13]
                                               : (const int*)itf;

    const int SK_SMEM = (128 * 129 + 128 * 3 + 256 + 256) * 4;  // 69632 B
    cudaFuncSetAttribute(sinkhorn, cudaFuncAttributeMaxDynamicSharedMemorySize, SK_SMEM);

    // 0a) WkT = W_sK^T                 [256,1024] -> [1024,256]
    transpose_k<<<dim3(HW_ / 32, C_ / 32, 1), 256>>>(W_sK, WkT, C_, HW_, 0, 0);
    // 0b) FsT[b] = F_s[b]^T            [1024,256] -> [256,1024], batched
    transpose_k<<<dim3(C_ / 32, HW_ / 32, B_), 256>>>(
        F_s, FsT, HW_, C_, (long long)HW_ * C_, (long long)C_ * HW_);
    // 0c) bcomb, b_sV/T
    bcomb_kernel<<<C_, 256>>>(W_sK, b_aQ, bc);
    bscale_kernel<<<1, 256>>>(b_sV, bsV, 1.f / (float)T_);

    // 1) Wcomb = W_aQ @ WkT            [256,256] k=1024 (NN, BM=64)
    sgemm<64><<<dim3(4, 4, 1), 256>>>(
        W_aQ, WkT, nullptr, nullptr, Wc, C_, C_, HW_, 0, 0, 0, 0, 0);

    // 2) Qw = F_a @ Wcomb + bcomb      [2048,256] k=256 (NN, BM=64)
    sgemm<64><<<dim3(4, 32, 1), 256>>>(
        F_a, Wc, bc, nullptr, Qw, B_ * T_, C_, C_, 0, 0, 0, 0, 0);

    // 3) QK[b] = Qw[b] @ FsT[b]        batched [128,1024] k=256 (NN, BM=128)
    sgemm<128><<<dim3(16, 1, B_), 256>>>(
        Qw, FsT, nullptr, nullptr, QK, T_, HW_, C_,
        (long long)T_ * C_, (long long)C_ * HW_, (long long)T_ * HW_, 0, 0);

    // 4) masked softmax -> Kmat (in place)
    softmax_kmat<<<B_ * T_, 256>>>(QK, M_s);

    // 5) Sinkhorn OT -> u, v
    sinkhorn<<<dim3(8, B_), 256, SK_SMEM>>>(QK, M_s, iterp, u, v);

    // 6) S_hat = u ⊙ Kmat ⊙ v (in place)
    scale_uv<<<B_ * T_, 256>>>(QK, u, v);

    // 7) G[b] = S_hat[b] @ F_s[b]      batched [128,256] k=1024 (NN, BM=64)
    sgemm<64><<<dim3(4, 2, B_), 256>>>(
        QK, F_s, nullptr, nullptr, G, T_, C_, HW_,
        (long long)T_ * HW_, (long long)HW_ * C_, (long long)T_ * C_, 0, 0);

    // 8) O = G @ W_sV + b_sV/T         [2048,256] k=256 (NN, BM=64)
    //    (row sums of S_hat are exactly 1/T after the final u-update)
    sgemm<64><<<dim3(4, 32, 1), 256>>>(
        G, W_sV, bsV, nullptr, O, B_ * T_, C_, C_, 0, 0, 0, 0, 0);

    // 9) H = relu(O @ W1 + b1)         [2048,768] k=256 (NN, BM=128)
    sgemm<128><<<dim3(12, 16, 1), 256>>>(
        O, W1, b1, nullptr, H, B_ * T_, 3 * C_, C_, 0, 0, 0, 0, 1);

    // 10) y = H @ W2 + b2 -> d_out     [2048,256] k=768 (NN, BM=64)
    sgemm<64><<<dim3(4, 32, 1), 256>>>(
        H, W2, b2, nullptr, y, B_ * T_, C_, 3 * C_, 0, 0, 0, 0, 0);
}